// round 3
// baseline (speedup 1.0000x reference)
#include <cuda_runtime.h>
#include <cstdint>

// ---------------------------------------------------------------------------
// Myloss2: mean( Loss + hinge(x, y) ) over 8*64*256*256 elements.
// NOTE: y is int32 on disk (JAX x64-disabled demotes jnp.int64 -> int32).
//   hi = SEG[y] = 1 - 0.25*y ; lo = hi - 0.25   (SEG affine)
//   hinge = relu(lo - x)^2 + relu(x - hi)^2, zeroed when y outside [0,4).
// Streaming HBM-bound reduction: 12 B/elem read (~403 MB total).
// ---------------------------------------------------------------------------

#define NBLOCKS   2048
#define NTHREADS  256

__device__ float g_partials[NBLOCKS];

__device__ __forceinline__ float hinge_elem(float x, int y, float L) {
    float fy = (float)y;
    float hi = fmaf(-0.25f, fy, 1.0f);
    float lo = hi - 0.25f;
    float a  = fmaxf(lo - x, 0.0f);
    float b  = fmaxf(x - hi, 0.0f);
    float h  = fmaf(a, a, b * b);
    bool valid = ((unsigned)y) < 4u;   // covers y<0 and y>=4
    return valid ? (L + h) : L;
}

__device__ __forceinline__ float hinge_vec4(float4 xv, int4 yv, float4 lv) {
    float s0 = hinge_elem(xv.x, yv.x, lv.x);
    float s1 = hinge_elem(xv.y, yv.y, lv.y);
    float s2 = hinge_elem(xv.z, yv.z, lv.z);
    float s3 = hinge_elem(xv.w, yv.w, lv.w);
    return (s0 + s1) + (s2 + s3);
}

__global__ void __launch_bounds__(NTHREADS)
hinge_partial_kernel(const float* __restrict__ x,
                     const int* __restrict__ y,
                     const float* __restrict__ Loss,
                     int nvec /* number of float4 groups */) {
    const float4* x4 = (const float4*)x;
    const float4* L4 = (const float4*)Loss;
    const int4*   y4 = (const int4*)y;

    const int tid    = blockIdx.x * blockDim.x + threadIdx.x;
    const int stride = gridDim.x * blockDim.x;

    float acc0 = 0.0f, acc1 = 0.0f;

    // Main loop: two independent legs per iteration -> 6 outstanding LDG.128
    // per thread per iteration, two independent FP accumulation chains.
    int i = tid;
    for (; i + stride < nvec; i += 2 * stride) {
        float4 xa = x4[i];
        int4   ya = y4[i];
        float4 la = L4[i];
        float4 xb = x4[i + stride];
        int4   yb = y4[i + stride];
        float4 lb = L4[i + stride];
        acc0 += hinge_vec4(xa, ya, la);
        acc1 += hinge_vec4(xb, yb, lb);
    }
    if (i < nvec) {
        acc0 += hinge_vec4(x4[i], y4[i], L4[i]);
    }
    float acc = acc0 + acc1;

    // warp reduce
    #pragma unroll
    for (int off = 16; off > 0; off >>= 1)
        acc += __shfl_xor_sync(0xFFFFFFFFu, acc, off);

    __shared__ float warp_sums[NTHREADS / 32];
    int lane = threadIdx.x & 31;
    int wid  = threadIdx.x >> 5;
    if (lane == 0) warp_sums[wid] = acc;
    __syncthreads();

    if (wid == 0) {
        float v = (lane < NTHREADS / 32) ? warp_sums[lane] : 0.0f;
        #pragma unroll
        for (int off = 16; off > 0; off >>= 1)
            v += __shfl_xor_sync(0xFFFFFFFFu, v, off);
        if (lane == 0) g_partials[blockIdx.x] = v;
    }
}

__global__ void __launch_bounds__(1024)
final_reduce_kernel(float* __restrict__ out, double inv_n) {
    double v = 0.0;
    for (int i = threadIdx.x; i < NBLOCKS; i += 1024)
        v += (double)g_partials[i];

    #pragma unroll
    for (int off = 16; off > 0; off >>= 1)
        v += __shfl_xor_sync(0xFFFFFFFFu, v, off);

    __shared__ double warp_sums[32];
    int lane = threadIdx.x & 31;
    int wid  = threadIdx.x >> 5;
    if (lane == 0) warp_sums[wid] = v;
    __syncthreads();

    if (wid == 0) {
        double s = (lane < 32) ? warp_sums[lane] : 0.0;
        #pragma unroll
        for (int off = 16; off > 0; off >>= 1)
            s += __shfl_xor_sync(0xFFFFFFFFu, s, off);
        if (lane == 0) out[0] = (float)(s * inv_n);
    }
}

extern "C" void kernel_launch(void* const* d_in, const int* in_sizes, int n_in,
                              void* d_out, int out_size) {
    const float* x    = (const float*)d_in[0];
    const int*   y    = (const int*)d_in[1];
    const float* Loss = (const float*)d_in[2];
    float*       out  = (float*)d_out;

    int n    = in_sizes[0];          // 33,554,432
    int nvec = n >> 2;               // divisible by 4

    hinge_partial_kernel<<<NBLOCKS, NTHREADS>>>(x, y, Loss, nvec);
    final_reduce_kernel<<<1, 1024>>>(out, 1.0 / (double)n);
}